// round 16
// baseline (speedup 1.0000x reference)
#include <cuda_runtime.h>
#include <cuda_bf16.h>
#include <cuda_fp16.h>
#include <cstdint>

// Problem constants (V,E,L,H = 128,512,8,8; B,T = 4,1024)
#define Bsz 4
#define Tt  1024
#define Vv  128
#define Ee  512
#define Hh  8
#define Ll  8
#define DH  64
#define NTOK (Bsz*Tt)          // 4096
#define QKVDIM (3*Ee)          // 1536
#define HCH (3*DH)             // 192

// weight hi/lo arena offsets (halves)
#define NW_QKV (Ll*QKVDIM*Ee)
#define NW_E   (Ll*Ee*Ee)
#define OFF_AFF1 (NW_QKV)
#define OFF_AFF2 (OFF_AFF1 + NW_E)
#define OFF_FFN1 (OFF_AFF2 + NW_E)
#define OFF_FFN2 (OFF_FFN1 + NW_E)
#define OFF_HEAD (OFF_FFN2 + NW_E)
#define NW_TOTAL (OFF_HEAD + Vv*Ee)

// ---------------- scratch (device globals; no allocation allowed) -----------
__device__ float g_x   [NTOK*Ee];
__device__ float g_aff [NTOK*Ee];
__device__ float g_out1[NTOK*Ee];
__device__ float g_logits[NTOK*Vv];
__device__ float g_partials[512];
__device__ int   g_is32;

__device__ __half g_wh[NW_TOTAL];
__device__ __half g_wl[NW_TOTAL];
__device__ __half g_qkvh[NTOK*QKVDIM], g_qkvl[NTOK*QKVDIM];
__device__ __half g_xh  [NTOK*Ee], g_xl  [NTOK*Ee];
__device__ __half g_atth[NTOK*Ee], g_attl[NTOK*Ee];
__device__ __half g_tmph[NTOK*Ee], g_tmpl[NTOK*Ee];
__device__ __half g_o1h [NTOK*Ee], g_o1l [NTOK*Ee];

extern __shared__ __align__(1024) char dynsmem[];

// ---------------- misc helpers -----------------------------------------------
__device__ __forceinline__ float warp_sum(float v){
#pragma unroll
    for (int o = 16; o; o >>= 1) v += __shfl_xor_sync(0xffffffffu, v, o);
    return v;
}
__device__ __forceinline__ float warp_max(float v){
#pragma unroll
    for (int o = 16; o; o >>= 1) v = fmaxf(v, __shfl_xor_sync(0xffffffffu, v, o));
    return v;
}
__device__ __forceinline__ int get_tok(const void* p, int i){
    return g_is32 ? ((const int*)p)[i] : (int)((const long long*)p)[i];
}
__device__ __forceinline__ void hsplit(float x, __half &h, __half &l){
    h = __float2half_rn(x);
    l = __float2half_rn(x - __half2float(h));
}
__device__ __forceinline__ uint32_t s2u(const void* p){
    uint32_t a; asm("{ .reg .u64 t; cvta.to.shared.u64 t, %1; cvt.u32.u64 %0, t; }" : "=r"(a) : "l"(p)); return a;
}

// ---------------- fused prep: weight cvt + embed (+ inline token detect) -----
__global__ void prep_kernel(const float* __restrict__ qkv_w,
                            const float* __restrict__ aff1_w,
                            const float* __restrict__ aff2_w,
                            const float* __restrict__ ffn1_w,
                            const float* __restrict__ ffn2_w,
                            const float* __restrict__ head_w,
                            __half* __restrict__ wh, __half* __restrict__ wl,
                            const void* __restrict__ inp,
                            const float* __restrict__ emb,
                            float* __restrict__ x,
                            __half* __restrict__ xh, __half* __restrict__ xl){
    int bid = blockIdx.x;
    if (bid < 14400){
        const float* src; size_t base; int local;
        if      (bid <  6144){ src = qkv_w;  base = 0;        local = bid; }
        else if (bid <  8192){ src = aff1_w; base = OFF_AFF1; local = bid - 6144; }
        else if (bid < 10240){ src = aff2_w; base = OFF_AFF2; local = bid - 8192; }
        else if (bid < 12288){ src = ffn1_w; base = OFF_FFN1; local = bid - 10240; }
        else if (bid < 14336){ src = ffn2_w; base = OFF_FFN2; local = bid - 12288; }
        else                 { src = head_w; base = OFF_HEAD; local = bid - 14336; }
        size_t i = (size_t)local*1024 + threadIdx.x*4;
        float4 v = *(const float4*)(src + i);
        __half h0,l0,h1,l1,h2,l2,h3,l3;
        hsplit(v.x,h0,l0); hsplit(v.y,h1,l1); hsplit(v.z,h2,l2); hsplit(v.w,h3,l3);
        *(__half2*)(wh + base + i)     = __halves2half2(h0,h1);
        *(__half2*)(wh + base + i + 2) = __halves2half2(h2,h3);
        *(__half2*)(wl + base + i)     = __halves2half2(l0,l1);
        *(__half2*)(wl + base + i + 2) = __halves2half2(l2,l3);
    } else {
        int t = bid - 14400;
        if (threadIdx.x >= 128) return;
        int is32 = 0;
        const int* ip = (const int*)inp;
        for (int i = 1; i < 128; i += 2) if (ip[i] != 0) { is32 = 1; break; }
        if (t == 0 && threadIdx.x == 0) g_is32 = is32;
        int tok = is32 ? ip[t] : (int)((const long long*)inp)[t];
        size_t off = (size_t)t*Ee + threadIdx.x*4;
        float4 v = *(const float4*)(emb + (size_t)tok*Ee + threadIdx.x*4);
        *(float4*)(x + off) = v;
        __half h0,l0,h1,l1,h2,l2,h3,l3;
        hsplit(v.x,h0,l0); hsplit(v.y,h1,l1); hsplit(v.z,h2,l2); hsplit(v.w,h3,l3);
        *(__half2*)(xh + off)     = __halves2half2(h0,h1);
        *(__half2*)(xh + off + 2) = __halves2half2(h2,h3);
        *(__half2*)(xl + off)     = __halves2half2(l0,l1);
        *(__half2*)(xl + off + 2) = __halves2half2(l2,l3);
    }
}

// ================= fp16 split-precision mma.sync GEMM (512 threads) ==========
#define KC 32
#define SSTR 40
#define TILEH (128*SSTR)
#define TEN_B (TILEH*2)
#define GEMM_SMEM_BYTES (2*4*TEN_B)    // 81920

__device__ __forceinline__ void mma16816(float* c, const uint32_t* a, const uint32_t* b){
    asm volatile("mma.sync.aligned.m16n8k16.row.col.f32.f16.f16.f32 "
        "{%0,%1,%2,%3}, {%4,%5,%6,%7}, {%8,%9}, {%0,%1,%2,%3};"
        : "+f"(c[0]), "+f"(c[1]), "+f"(c[2]), "+f"(c[3])
        : "r"(a[0]), "r"(a[1]), "r"(a[2]), "r"(a[3]), "r"(b[0]), "r"(b[1]));
}
#define LDSM4(r0,r1,r2,r3,addr) \
    asm volatile("ldmatrix.sync.aligned.m8n8.x4.shared.b16 {%0,%1,%2,%3}, [%4];" \
        : "=r"(r0), "=r"(r1), "=r"(r2), "=r"(r3) : "r"(addr))
#define LDSM4T(r0,r1,r2,r3,addr) \
    asm volatile("ldmatrix.sync.aligned.m8n8.x4.trans.shared.b16 {%0,%1,%2,%3}, [%4];" \
        : "=r"(r0), "=r"(r1), "=r"(r2), "=r"(r3) : "r"(addr))

__global__ __launch_bounds__(512, 1)
void gemm_tc_kernel(const __half* __restrict__ Ahg, const __half* __restrict__ Alg,
                    const __half* __restrict__ Whg, const __half* __restrict__ Wlg,
                    const float* __restrict__ bias,
                    float* __restrict__ C,
                    __half* __restrict__ Chi, __half* __restrict__ Clo,
                    int N, int K, int doRelu){
    __half* sm = (__half*)dynsmem;
    uint32_t sb = s2u(dynsmem);
    int tid = threadIdx.x, wid = tid >> 5, lane = tid & 31;
    int warpM = wid >> 2, warpN = wid & 3;
    int rowBase = blockIdx.y * 128, colBase = blockIdx.x * 128;

    int srow = tid >> 2;
    int skq  = (tid & 3) * 8;
    const __half* aSh = Ahg + (size_t)(rowBase + srow)*K + skq;
    const __half* aSl = Alg + (size_t)(rowBase + srow)*K + skq;
    const __half* wSh = Whg + (size_t)(colBase + srow)*K + skq;
    const __half* wSl = Wlg + (size_t)(colBase + srow)*K + skq;
    int sbase = srow*SSTR + skq;

    uint32_t arow_off = (uint32_t)((warpM*32 + (lane & 15))*SSTR*2 + (lane >> 4)*16);
    uint32_t brow_off = (uint32_t)((warpN*32 + (lane >> 4)*8 + (lane & 7))*SSTR*2
                                   + ((lane >> 3) & 1)*16);

    float acc[2][4][4];
#pragma unroll
    for (int i = 0; i < 2; i++)
#pragma unroll
        for (int j = 0; j < 4; j++)
#pragma unroll
            for (int q = 0; q < 4; q++) acc[i][j][q] = 0.f;

    {
        __half* B0 = sm;
        *(uint4*)(B0 + sbase)           = *(const uint4*)(aSh);
        *(uint4*)(B0 + TILEH + sbase)   = *(const uint4*)(aSl);
        *(uint4*)(B0 + 2*TILEH + sbase) = *(const uint4*)(wSh);
        *(uint4*)(B0 + 3*TILEH + sbase) = *(const uint4*)(wSl);
    }
    __syncthreads();

    int nch = K / KC;
    for (int c = 0; c < nch; c++){
        if (c + 1 < nch){
            __half* nB = sm + ((c+1) & 1)*4*TILEH;
            *(uint4*)(nB + sbase)           = *(const uint4*)(aSh + (c+1)*KC);
            *(uint4*)(nB + TILEH + sbase)   = *(const uint4*)(aSl + (c+1)*KC);
            *(uint4*)(nB + 2*TILEH + sbase) = *(const uint4*)(wSh + (c+1)*KC);
            *(uint4*)(nB + 3*TILEH + sbase) = *(const uint4*)(wSl + (c+1)*KC);
        }

        uint32_t bufA = sb + (uint32_t)((c & 1)*4*TEN_B);
#pragma unroll
        for (int ks = 0; ks < 2; ks++){
            uint32_t kkb = (uint32_t)(ks*32);
            uint32_t aH = bufA + arow_off + kkb;
            uint32_t aL = aH + TEN_B;
            uint32_t bH = bufA + 2*TEN_B + brow_off + kkb;
            uint32_t bL = bH + TEN_B;

            uint32_t ah[2][4], al[2][4], bh[4][2], bl[4][2];
#pragma unroll
            for (int mt = 0; mt < 2; mt++){
                LDSM4(ah[mt][0], ah[mt][1], ah[mt][2], ah[mt][3], aH + mt*16*SSTR*2);
                LDSM4(al[mt][0], al[mt][1], al[mt][2], al[mt][3], aL + mt*16*SSTR*2);
            }
#pragma unroll
            for (int p = 0; p < 2; p++){
                LDSM4(bh[2*p][0], bh[2*p][1], bh[2*p+1][0], bh[2*p+1][1], bH + p*16*SSTR*2);
                LDSM4(bl[2*p][0], bl[2*p][1], bl[2*p+1][0], bl[2*p+1][1], bL + p*16*SSTR*2);
            }
#pragma unroll
            for (int mt = 0; mt < 2; mt++)
#pragma unroll
                for (int nt = 0; nt < 4; nt++){
                    mma16816(acc[mt][nt], ah[mt], bh[nt]);
                    mma16816(acc[mt][nt], ah[mt], bl[nt]);
                    mma16816(acc[mt][nt], al[mt], bh[nt]);
                }
        }
        __syncthreads();
    }

    int r  = lane >> 2;
    int cp = (lane & 3) * 2;
#pragma unroll
    for (int mt = 0; mt < 2; mt++){
        int r0 = rowBase + warpM*32 + mt*16 + r;
#pragma unroll
        for (int nt = 0; nt < 4; nt++){
            int c0 = colBase + warpN*32 + nt*8 + cp;
            float b0 = bias[c0], b1 = bias[c0+1];
            float v0 = acc[mt][nt][0] + b0, v1 = acc[mt][nt][1] + b1;
            float v2 = acc[mt][nt][2] + b0, v3 = acc[mt][nt][3] + b1;
            if (doRelu){
                v0 = fmaxf(v0, 0.f); v1 = fmaxf(v1, 0.f);
                v2 = fmaxf(v2, 0.f); v3 = fmaxf(v3, 0.f);
            }
            if (C){
                *(float2*)(C + (size_t)r0*N + c0)     = make_float2(v0, v1);
                *(float2*)(C + (size_t)(r0+8)*N + c0) = make_float2(v2, v3);
            }
            if (Chi){
                __half h0,l0,h1,l1,h2,l2,h3,l3;
                hsplit(v0,h0,l0); hsplit(v1,h1,l1); hsplit(v2,h2,l2); hsplit(v3,h3,l3);
                *(__half2*)(Chi + (size_t)r0*N + c0)     = __halves2half2(h0,h1);
                *(__half2*)(Chi + (size_t)(r0+8)*N + c0) = __halves2half2(h2,h3);
                *(__half2*)(Clo + (size_t)r0*N + c0)     = __halves2half2(l0,l1);
                *(__half2*)(Clo + (size_t)(r0+8)*N + c0) = __halves2half2(l2,l3);
            }
        }
    }
}

// ================= flash attention via mma.sync (self-contained) =============
// All 16 j-tiles processed. Masked score == 0 exactly -> weight exp(0)=1:
//   causal tiles: p = (col<=qi) ? exp(s*scale) : 1   (exact semantics)
//   fully-masked tiles (jt>qt): P = ones, skip S/K entirely; l += 64/tile.
// No suffix-sum kernel, no tail. qt order reversed for load balance.
#define QSTR 72
#define ATILE_H (64*QSTR)
#define ATILE_B (ATILE_H*2)            // 9216 bytes
#define SM_QH 0
#define SM_QL ATILE_B
#define SM_KV (2*ATILE_B)
#define KVBUF_B (4*ATILE_B)
#define FLASH_SMEM (SM_KV + 2*KVBUF_B) // 92160

__global__ __launch_bounds__(128, 1)
void flash_attn_kernel(const __half* __restrict__ qkvh, const __half* __restrict__ qkvl,
                       __half* __restrict__ oh, __half* __restrict__ ol){
    __half* sm = (__half*)dynsmem;
    uint32_t sb = s2u(dynsmem);
    int tid = threadIdx.x, wid = tid >> 5, lane = tid & 31;
    int bh = blockIdx.x, b = bh >> 3, h = bh & 7;
    int qt = (gridDim.y - 1) - blockIdx.y;   // heavy tiles launch first

    int srow = tid >> 1;
    int scol = (tid & 1) * 32;
    size_t qtokoff = (size_t)(b*Tt + qt*64 + srow)*QKVDIM + h*HCH + scol;
    int sdst = srow*QSTR + scol;

    // stage Q (hi/lo)
    {
        const __half* qh = qkvh + qtokoff;
        const __half* ql = qkvl + qtokoff;
        __half* dQh = sm + SM_QH/2;
        __half* dQl = sm + SM_QL/2;
#pragma unroll
        for (int i = 0; i < 4; i++){
            *(uint4*)(dQh + sdst + i*8) = *(const uint4*)(qh + i*8);
            *(uint4*)(dQl + sdst + i*8) = *(const uint4*)(ql + i*8);
        }
    }
    // stage KV tile 0 (always causal: qt >= 0)
    {
        size_t ktok = (size_t)(b*Tt + srow)*QKVDIM + h*HCH + DH + scol;
        size_t vtok = ktok + DH;
        __half* base = sm + SM_KV/2;
#pragma unroll
        for (int i = 0; i < 4; i++){
            *(uint4*)(base + sdst + i*8)             = *(const uint4*)(qkvh + ktok + i*8);
            *(uint4*)(base + ATILE_H + sdst + i*8)   = *(const uint4*)(qkvl + ktok + i*8);
            *(uint4*)(base + 2*ATILE_H + sdst + i*8) = *(const uint4*)(qkvh + vtok + i*8);
            *(uint4*)(base + 3*ATILE_H + sdst + i*8) = *(const uint4*)(qkvl + vtok + i*8);
        }
    }
    __syncthreads();

    int r  = lane >> 2;
    int cq = lane & 3;
    int qi0 = qt*64 + wid*16 + r;
    int qi1 = qi0 + 8;

    uint32_t aoff = (uint32_t)((wid*16 + (lane & 15))*QSTR*2 + (lane >> 4)*16);
    uint32_t boff = (uint32_t)(((lane >> 4)*8 + (lane & 7))*QSTR*2 + ((lane >> 3) & 1)*16);
    uint32_t voff = (uint32_t)((lane & 15)*QSTR*2 + (lane >> 4)*16);

    const uint32_t ONES2 = 0x3C003C00u;   // fp16 {1,1}

    float O[8][4];
#pragma unroll
    for (int i = 0; i < 8; i++)
#pragma unroll
        for (int q = 0; q < 4; q++) O[i][q] = 0.f;
    float l0 = 0.f, l1 = 0.f;

    const int NJT = Tt/64;   // 16
    for (int jt = 0; jt < NJT; jt++){
        // prefetch next tile: V always; K only if next tile is causal
        if (jt + 1 < NJT){
            size_t ktok = (size_t)(b*Tt + (jt+1)*64 + srow)*QKVDIM + h*HCH + DH + scol;
            size_t vtok = ktok + DH;
            __half* base = sm + SM_KV/2 + ((jt+1) & 1)*(KVBUF_B/2);
            if (jt + 1 <= qt){
#pragma unroll
                for (int i = 0; i < 4; i++){
                    *(uint4*)(base + sdst + i*8)           = *(const uint4*)(qkvh + ktok + i*8);
                    *(uint4*)(base + ATILE_H + sdst + i*8) = *(const uint4*)(qkvl + ktok + i*8);
                }
            }
#pragma unroll
            for (int i = 0; i < 4; i++){
                *(uint4*)(base + 2*ATILE_H + sdst + i*8) = *(const uint4*)(qkvh + vtok + i*8);
                *(uint4*)(base + 3*ATILE_H + sdst + i*8) = *(const uint4*)(qkvl + vtok + i*8);
            }
        }

        uint32_t kvb = sb + SM_KV + (uint32_t)((jt & 1)*KVBUF_B);
        uint32_t KH = kvb, KL = kvb + ATILE_B, VH = kvb + 2*ATILE_B, VL = kvb + 3*ATILE_B;

        uint32_t P[4][4];
        if (jt <= qt){
            // ---- S = Q@K^T (3-pass hi/lo), fp32 accum ----
            float S[8][4];
#pragma unroll
            for (int i = 0; i < 8; i++)
#pragma unroll
                for (int q = 0; q < 4; q++) S[i][q] = 0.f;

#pragma unroll
            for (int ks = 0; ks < 4; ks++){
                uint32_t kb = (uint32_t)(ks*32);
                uint32_t ah[4], al[4], bh[4][2], bl[4][2];
                LDSM4(ah[0], ah[1], ah[2], ah[3], sb + SM_QH + aoff + kb);
                LDSM4(al[0], al[1], al[2], al[3], sb + SM_QL + aoff + kb);
#pragma unroll
                for (int p = 0; p < 2; p++){
                    LDSM4(bh[2*p][0], bh[2*p][1], bh[2*p+1][0], bh[2*p+1][1],
                          KH + boff + kb + p*16*QSTR*2);
                    LDSM4(bl[2*p][0], bl[2*p][1], bl[2*p+1][0], bl[2*p+1][1],
                          KL + boff + kb + p*16*QSTR*2);
                }
#pragma unroll
                for (int p = 0; p < 2; p++){
#pragma unroll
                    for (int q2 = 0; q2 < 2; q2++){
                        int nt = 2*p + q2;
                        mma16816(S[nt], ah, bh[nt]);
                        mma16816(S[nt], ah, bl[nt]);
                        mma16816(S[nt], al, bh[nt]);
                    }
                }
#pragma unroll
                for (int p = 0; p < 2; p++){
                    uint32_t b2h[2][2], b2l[2][2];
                    LDSM4(b2h[0][0], b2h[0][1], b2h[1][0], b2h[1][1],
                          KH + boff + kb + (p+2)*16*QSTR*2);
                    LDSM4(b2l[0][0], b2l[0][1], b2l[1][0], b2l[1][1],
                          KL + boff + kb + (p+2)*16*QSTR*2);
#pragma unroll
                    for (int q2 = 0; q2 < 2; q2++){
                        int nt = 4 + 2*p + q2;
                        mma16816(S[nt], ah, b2h[q2]);
                        mma16816(S[nt], ah, b2l[q2]);
                        mma16816(S[nt], al, b2h[q2]);
                    }
                }
            }

            // ---- mask + exp (masked weight = exp(0) = 1) + l + fp16 P ----
#pragma unroll
            for (int n = 0; n < 8; n++){
                int colb = jt*64 + n*8 + cq*2;
                float e0 = __expf(fminf(S[n][0]*0.125f, 80.f));
                float e1 = __expf(fminf(S[n][1]*0.125f, 80.f));
                float e2 = __expf(fminf(S[n][2]*0.125f, 80.f));
                float e3 = __expf(fminf(S[n][3]*0.125f, 80.f));
                float p0 = (colb     <= qi0) ? e0 : 1.f;
                float p1 = (colb + 1 <= qi0) ? e1 : 1.f;
                float p2 = (colb     <= qi1) ? e2 : 1.f;
                float p3 = (colb + 1 <= qi1) ? e3 : 1.f;
                l0 += p0 + p1;
                l1 += p2 + p3;
                uint32_t h01, h23;
                asm("cvt.rn.f16x2.f32 %0, %1, %2;" : "=r"(h01) : "f"(p1), "f"(p0));
                asm("cvt.rn.f16x2.f32 %0, %1, %2;" : "=r"(h23) : "f"(p3), "f"(p2));
                int ks2 = n >> 1;
                if ((n & 1) == 0){ P[ks2][0] = h01; P[ks2][1] = h23; }
                else             { P[ks2][2] = h01; P[ks2][3] = h23; }
            }
        } else {
            // fully-masked tile: all weights exactly 1
#pragma unroll
            for (int k2 = 0; k2 < 4; k2++)
#pragma unroll
                for (int q2 = 0; q2 < 4; q2++) P[k2][q2] = ONES2;
        }

        // ---- O += P@V (2-pass: Vh, Vl) ----
#pragma unroll
        for (int ks = 0; ks < 4; ks++){
            uint32_t krow = (uint32_t)(ks*16*QSTR*2);
#pragma unroll
            for (int p = 0; p < 4; p++){
                uint32_t bvh[2][2], bvl[2][2];
                LDSM4T(bvh[0][0], bvh[0][1], bvh[1][0], bvh[1][1],
                       VH + krow + voff + p*32);
                LDSM4T(bvl[0][0], bvl[0][1], bvl[1][0], bvl[1][1],
                       VL + krow + voff + p*32);
                mma16816(O[2*p],   P[ks], bvh[0]);
                mma16816(O[2*p],   P[ks], bvl[0]);
                mma16816(O[2*p+1], P[ks], bvh[1]);
                mma16816(O[2*p+1], P[ks], bvl[1]);
            }
        }
        __syncthreads();
    }

    // quad-reduce l and add ones-tile counts
    unsigned qmask = 0xFu << (lane & 28);
    l0 += __shfl_xor_sync(qmask, l0, 1); l0 += __shfl_xor_sync(qmask, l0, 2);
    l1 += __shfl_xor_sync(qmask, l1, 1); l1 += __shfl_xor_sync(qmask, l1, 2);
    float onesl = 64.f * (float)(NJT - 1 - qt);
    l0 += onesl;
    l1 += onesl;

    float inv0 = 1.f / l0, inv1 = 1.f / l1;
    size_t ob0 = (size_t)(b*Tt + qi0)*Ee + h*DH;
    size_t ob1 = (size_t)(b*Tt + qi1)*Ee + h*DH;
#pragma unroll
    for (int n = 0; n < 8; n++){
        int d0 = n*8 + cq*2;
        float v0 = O[n][0]*inv0, v1 = O[n][1]*inv0;
        float v2 = O[n][2]*inv1, v3 = O[n][3]*inv1;
        __half h0,lo0,h1,lo1,h2,lo2,h3,lo3;
        hsplit(v0,h0,lo0); hsplit(v1,h1,lo1); hsplit(v2,h2,lo2); hsplit(v3,h3,lo3);
        *(__half2*)(oh + ob0 + d0) = __halves2half2(h0,h1);
        *(__half2*)(ol + ob0 + d0) = __halves2half2(lo0,lo1);
        *(__half2*)(oh + ob1 + d0) = __halves2half2(h2,h3);
        *(__half2*)(ol + ob1 + d0) = __halves2half2(lo2,lo3);
    }
}

// ---------------- fused residual-add + LayerNorm (fp32 + hi/lo out) ----------
__global__ void add_ln_kernel(const float* __restrict__ a, const float* __restrict__ b,
                              const float* __restrict__ gam, const float* __restrict__ bet,
                              float* __restrict__ out,
                              __half* __restrict__ outh, __half* __restrict__ outl){
    int warp = threadIdx.x >> 5, lane = threadIdx.x & 31;
    int row = blockIdx.x * 8 + warp;
    size_t rb = (size_t)row*Ee;
    float xs[16];
    float sum = 0.f, sq = 0.f;
#pragma unroll
    for (int c = 0; c < 4; c++) {
        size_t off = rb + c*128 + lane*4;
        float4 va = *(const float4*)(a + off);
        float4 vb = *(const float4*)(b + off);
        float x0 = va.x+vb.x, x1 = va.y+vb.y, x2 = va.z+vb.z, x3 = va.w+vb.w;
        xs[c*4+0]=x0; xs[c*4+1]=x1; xs[c*4+2]=x2; xs[c*4+3]=x3;
        sum += x0+x1+x2+x3;
        sq  += x0*x0+x1*x1+x2*x2+x3*x3;
    }
    sum = warp_sum(sum);
    sq  = warp_sum(sq);
    float mean = sum * (1.f/(float)Ee);
    float var  = sq  * (1.f/(float)Ee) - mean*mean;
    float r = rsqrtf(var + 1e-5f);
#pragma unroll
    for (int c = 0; c < 4; c++) {
        int col = c*128 + lane*4;
        float4 g  = *(const float4*)(gam + col);
        float4 be = *(const float4*)(bet + col);
        float y0 = (xs[c*4+0]-mean)*r*g.x + be.x;
        float y1 = (xs[c*4+1]-mean)*r*g.y + be.y;
        float y2 = (xs[c*4+2]-mean)*r*g.z + be.z;
        float y3 = (xs[c*4+3]-mean)*r*g.w + be.w;
        *(float4*)(out + rb + col) = make_float4(y0,y1,y2,y3);
        __half h0,l0,h1,l1,h2,l2,h3,l3;
        hsplit(y0,h0,l0); hsplit(y1,h1,l1); hsplit(y2,h2,l2); hsplit(y3,h3,l3);
        *(__half2*)(outh + rb + col)     = __halves2half2(h0,h1);
        *(__half2*)(outh + rb + col + 2) = __halves2half2(h2,h3);
        *(__half2*)(outl + rb + col)     = __halves2half2(l0,l1);
        *(__half2*)(outl + rb + col + 2) = __halves2half2(l2,l3);
    }
}

// ---------------- loss -------------------------------------------------------
__global__ void loss_rows_kernel(const float* __restrict__ logits,
                                 const void* __restrict__ tgt,
                                 float* __restrict__ partials){
    __shared__ float rvals[8];
    int warp = threadIdx.x >> 5, lane = threadIdx.x & 31;
    int row = blockIdx.x * 8 + warp;
    const float* lp = logits + (size_t)row*Vv;
    float4 v = *(const float4*)(lp + lane*4);
    float mx = warp_max(fmaxf(fmaxf(v.x, v.y), fmaxf(v.z, v.w)));
    float sm = warp_sum(v.x + v.y + v.z + v.w);
    float se = warp_sum(__expf(v.x-mx) + __expf(v.y-mx) + __expf(v.z-mx) + __expf(v.w-mx));
    if (lane == 0) {
        float logZ = mx + logf(se);
        int t = get_tok(tgt, row);
        float nll    = logZ - lp[t];
        float smooth = logZ - sm * (1.f/(float)Vv);
        rvals[warp] = 0.9f*nll + 0.1f*smooth;
    }
    __syncthreads();
    if (threadIdx.x == 0) {
        float s = 0.f;
        for (int i = 0; i < 8; i++) s += rvals[i];
        partials[blockIdx.x] = s;
    }
}

__global__ void loss_final_kernel(const float* __restrict__ partials, float* __restrict__ out){
    __shared__ float s[512];
    int tid = threadIdx.x;
    s[tid] = partials[tid];
    __syncthreads();
    for (int o = 256; o; o >>= 1) {
        if (tid < o) s[tid] += s[tid + o];
        __syncthreads();
    }
    if (tid == 0) out[0] = s[0] * (1.f/(float)NTOK);
}

// ---------------- launch ------------------------------------------------------
extern "C" void kernel_launch(void* const* d_in, const int* in_sizes, int n_in,
                              void* d_out, int out_size){
    const void *inputs, *targets;
    const float *emb, *qkv_w, *qkv_b, *aff1_w, *aff1_b, *aff2_w, *aff2_b;
    const float *ffn1_w, *ffn1_b, *ffn2_w, *ffn2_b;
    const float *ln1_s, *ln1_b, *ln2_s, *ln2_b, *head_w, *head_b;

    if (in_sizes[1] > 100000) {
        aff1_b = (const float*)d_in[0];
        aff1_w = (const float*)d_in[1];
        aff2_b = (const float*)d_in[2];
        aff2_w = (const float*)d_in[3];
        emb    = (const float*)d_in[4];
        ffn1_b = (const float*)d_in[5];
        ffn1_w = (const float*)d_in[6];
        ffn2_b = (const float*)d_in[7];
        ffn2_w = (const float*)d_in[8];
        head_b = (const float*)d_in[9];
        head_w = (const float*)d_in[10];
        inputs = d_in[11];
        ln1_b  = (const float*)d_in[12];
        ln1_s  = (const float*)d_in[13];
        ln2_b  = (const float*)d_in[14];
        ln2_s  = (const float*)d_in[15];
        qkv_b  = (const float*)d_in[16];
        qkv_w  = (const float*)d_in[17];
        targets= d_in[18];
    } else {
        inputs  = d_in[0];
        targets = d_in[1];
        emb     = (const float*)d_in[2];
        qkv_w   = (const float*)d_in[3];
        qkv_b   = (const float*)d_in[4];
        aff1_w  = (const float*)d_in[5];
        aff1_b  = (const float*)d_in[6];
        aff2_w  = (const float*)d_in[7];
        aff2_b  = (const float*)d_in[8];
        ffn1_w  = (const float*)d_in[9];
        ffn1_b  = (const float*)d_in[10];
        ffn2_w  = (const float*)d_in[11];
        ffn2_b  = (const float*)d_in[12];
        ln1_s   = (const float*)d_in[13];
        ln1_b   = (const float*)d_in[14];
        ln2_s   = (const float*)d_in[15];
        ln2_b   = (const float*)d_in[16];
        head_w  = (const float*)d_in[17];
        head_b  = (const float*)d_in[18];
    }
    float* out = (float*)d_out;

    float *x, *aff, *out1, *logits_scratch, *partials;
    __half *wh, *wl, *xh, *xl, *atth, *attl, *tmph, *tmpl, *o1h, *o1l, *qkvh, *qkvl;
    cudaGetSymbolAddress((void**)&x,    g_x);
    cudaGetSymbolAddress((void**)&aff,  g_aff);
    cudaGetSymbolAddress((void**)&out1, g_out1);
    cudaGetSymbolAddress((void**)&logits_scratch, g_logits);
    cudaGetSymbolAddress((void**)&partials, g_partials);
    cudaGetSymbolAddress((void**)&wh,   g_wh);
    cudaGetSymbolAddress((void**)&wl,   g_wl);
    cudaGetSymbolAddress((void**)&xh,   g_xh);
    cudaGetSymbolAddress((void**)&xl,   g_xl);
    cudaGetSymbolAddress((void**)&atth, g_atth);
    cudaGetSymbolAddress((void**)&attl, g_attl);
    cudaGetSymbolAddress((void**)&tmph, g_tmph);
    cudaGetSymbolAddress((void**)&tmpl, g_tmpl);
    cudaGetSymbolAddress((void**)&o1h,  g_o1h);
    cudaGetSymbolAddress((void**)&o1l,  g_o1l);
    cudaGetSymbolAddress((void**)&qkvh, g_qkvh);
    cudaGetSymbolAddress((void**)&qkvl, g_qkvl);

    const int BTV = NTOK * Vv;
    float* logits_dst = (out_size >= BTV) ? out : logits_scratch;
    float* loss_dst   = (out_size > BTV) ? (out + BTV)
                       : ((out_size > 0 && out_size < BTV) ? out : nullptr);

    cudaFuncSetAttribute(gemm_tc_kernel, cudaFuncAttributeMaxDynamicSharedMemorySize, GEMM_SMEM_BYTES);
    cudaFuncSetAttribute(flash_attn_kernel, cudaFuncAttributeMaxDynamicSharedMemorySize, FLASH_SMEM);

    prep_kernel<<<18496, 256>>>(qkv_w, aff1_w, aff2_w, ffn1_w, ffn2_w, head_w,
                                wh, wl, inputs, emb, x, xh, xl);

    dim3 gQKV(QKVDIM/128, NTOK/128);
    dim3 gE  (Ee/128,     NTOK/128);
    dim3 gHead(Vv/128,    NTOK/128);
    dim3 gAtt(Bsz*Hh, Tt/64);          // (32,16)

    for (int l = 0; l < Ll; l++) {
        gemm_tc_kernel<<<gQKV, 512, GEMM_SMEM_BYTES>>>(
            xh, xl, wh + (size_t)l*QKVDIM*Ee, wl + (size_t)l*QKVDIM*Ee,
            qkv_b + (size_t)l*QKVDIM, nullptr, qkvh, qkvl, QKVDIM, Ee, 0);
        flash_attn_kernel<<<gAtt, 128, FLASH_SMEM>>>(qkvh, qkvl, atth, attl);
        gemm_tc_kernel<<<gE, 512, GEMM_SMEM_BYTES>>>(
            atth, attl, wh + OFF_AFF1 + (size_t)l*Ee*Ee, wl + OFF_AFF1 + (size_t)l*Ee*Ee,
            aff1_b + (size_t)l*Ee, nullptr, tmph, tmpl, Ee, Ee, 1);
        gemm_tc_kernel<<<gE, 512, GEMM_SMEM_BYTES>>>(
            tmph, tmpl, wh + OFF_AFF2 + (size_t)l*Ee*Ee, wl + OFF_AFF2 + (size_t)l*Ee*Ee,
            aff2_b + (size_t)l*Ee, aff, nullptr, nullptr, Ee, Ee, 0);
        add_ln_kernel<<<NTOK/8, 256>>>(aff, x, ln1_s + (size_t)l*Ee, ln1_b + (size_t)l*Ee,
                                       out1, o1h, o1l);
        gemm_tc_kernel<<<gE, 512, GEMM_SMEM_BYTES>>>(
            o1h, o1l, wh + OFF_FFN1 + (size_t)l*Ee*Ee, wl + OFF_FFN1 + (size_t)l*Ee*Ee,
            ffn1_b + (size_t)l*Ee, nullptr, tmph, tmpl, Ee, Ee, 1);
        gemm_tc_kernel<<<gE, 512, GEMM_SMEM_BYTES>>>(
            tmph, tmpl, wh + OFF_FFN2 + (size_t)l*Ee*Ee, wl + OFF_FFN2 + (size_t)l*Ee*Ee,
            ffn2_b + (size_t)l*Ee, aff, nullptr, nullptr, Ee, Ee, 0);
        add_ln_kernel<<<NTOK/8, 256>>>(out1, aff, ln2_s + (size_t)l*Ee, ln2_b + (size_t)l*Ee,
                                       x, xh, xl);
    }

    gemm_tc_kernel<<<gHead, 512, GEMM_SMEM_BYTES>>>(
        xh, xl, wh + OFF_HEAD, wl + OFF_HEAD, head_b,
        logits_dst, nullptr, nullptr, Vv, Ee, 0);
    loss_rows_kernel<<<NTOK/8, 256>>>(logits_dst, targets, partials);
    if (loss_dst)
        loss_final_kernel<<<1, 512>>>(partials, loss_dst);
}

// round 17
// speedup vs baseline: 1.4849x; 1.4849x over previous
#include <cuda_runtime.h>
#include <cuda_bf16.h>
#include <cuda_fp16.h>
#include <cstdint>

// Problem constants (V,E,L,H = 128,512,8,8; B,T = 4,1024)
#define Bsz 4
#define Tt  1024
#define Vv  128
#define Ee  512
#define Hh  8
#define Ll  8
#define DH  64
#define NTOK (Bsz*Tt)          // 4096
#define QKVDIM (3*Ee)          // 1536
#define HCH (3*DH)             // 192

// weight hi/lo arena offsets (halves)
#define NW_QKV (Ll*QKVDIM*Ee)
#define NW_E   (Ll*Ee*Ee)
#define OFF_AFF1 (NW_QKV)
#define OFF_AFF2 (OFF_AFF1 + NW_E)
#define OFF_FFN1 (OFF_AFF2 + NW_E)
#define OFF_FFN2 (OFF_FFN1 + NW_E)
#define OFF_HEAD (OFF_FFN2 + NW_E)
#define NW_TOTAL (OFF_HEAD + Vv*Ee)

// ---------------- scratch (device globals; no allocation allowed) -----------
__device__ float g_x   [NTOK*Ee];
__device__ float g_qkv [NTOK*QKVDIM];
__device__ float g_aff [NTOK*Ee];
__device__ float g_out1[NTOK*Ee];
__device__ float g_sv  [Bsz*Hh*Tt*DH];
__device__ float g_logits[NTOK*Vv];
__device__ float g_partials[512];
__device__ int   g_is32;

__device__ __half g_wh[NW_TOTAL];
__device__ __half g_wl[NW_TOTAL];
__device__ __half g_qkvh[NTOK*QKVDIM], g_qkvl[NTOK*QKVDIM];
__device__ __half g_xh  [NTOK*Ee], g_xl  [NTOK*Ee];
__device__ __half g_atth[NTOK*Ee], g_attl[NTOK*Ee];
__device__ __half g_tmph[NTOK*Ee], g_tmpl[NTOK*Ee];
__device__ __half g_o1h [NTOK*Ee], g_o1l [NTOK*Ee];

extern __shared__ __align__(1024) char dynsmem[];

// ---------------- misc helpers -----------------------------------------------
__device__ __forceinline__ float warp_sum(float v){
#pragma unroll
    for (int o = 16; o; o >>= 1) v += __shfl_xor_sync(0xffffffffu, v, o);
    return v;
}
__device__ __forceinline__ float warp_max(float v){
#pragma unroll
    for (int o = 16; o; o >>= 1) v = fmaxf(v, __shfl_xor_sync(0xffffffffu, v, o));
    return v;
}
__device__ __forceinline__ int get_tok(const void* p, int i){
    return g_is32 ? ((const int*)p)[i] : (int)((const long long*)p)[i];
}
__device__ __forceinline__ void hsplit(float x, __half &h, __half &l){
    h = __float2half_rn(x);
    l = __float2half_rn(x - __half2float(h));
}
__device__ __forceinline__ uint32_t s2u(const void* p){
    uint32_t a; asm("{ .reg .u64 t; cvta.to.shared.u64 t, %1; cvt.u32.u64 %0, t; }" : "=r"(a) : "l"(p)); return a;
}

// ---------------- fused prep: weight cvt + embed (+ inline token detect) -----
__global__ void prep_kernel(const float* __restrict__ qkv_w,
                            const float* __restrict__ aff1_w,
                            const float* __restrict__ aff2_w,
                            const float* __restrict__ ffn1_w,
                            const float* __restrict__ ffn2_w,
                            const float* __restrict__ head_w,
                            __half* __restrict__ wh, __half* __restrict__ wl,
                            const void* __restrict__ inp,
                            const float* __restrict__ emb,
                            float* __restrict__ x,
                            __half* __restrict__ xh, __half* __restrict__ xl){
    int bid = blockIdx.x;
    if (bid < 14400){
        const float* src; size_t base; int local;
        if      (bid <  6144){ src = qkv_w;  base = 0;        local = bid; }
        else if (bid <  8192){ src = aff1_w; base = OFF_AFF1; local = bid - 6144; }
        else if (bid < 10240){ src = aff2_w; base = OFF_AFF2; local = bid - 8192; }
        else if (bid < 12288){ src = ffn1_w; base = OFF_FFN1; local = bid - 10240; }
        else if (bid < 14336){ src = ffn2_w; base = OFF_FFN2; local = bid - 12288; }
        else                 { src = head_w; base = OFF_HEAD; local = bid - 14336; }
        size_t i = (size_t)local*1024 + threadIdx.x*4;
        float4 v = *(const float4*)(src + i);
        __half h0,l0,h1,l1,h2,l2,h3,l3;
        hsplit(v.x,h0,l0); hsplit(v.y,h1,l1); hsplit(v.z,h2,l2); hsplit(v.w,h3,l3);
        *(__half2*)(wh + base + i)     = __halves2half2(h0,h1);
        *(__half2*)(wh + base + i + 2) = __halves2half2(h2,h3);
        *(__half2*)(wl + base + i)     = __halves2half2(l0,l1);
        *(__half2*)(wl + base + i + 2) = __halves2half2(l2,l3);
    } else {
        int t = bid - 14400;
        if (threadIdx.x >= 128) return;
        int is32 = 0;
        const int* ip = (const int*)inp;
        for (int i = 1; i < 128; i += 2) if (ip[i] != 0) { is32 = 1; break; }
        if (t == 0 && threadIdx.x == 0) g_is32 = is32;
        int tok = is32 ? ip[t] : (int)((const long long*)inp)[t];
        size_t off = (size_t)t*Ee + threadIdx.x*4;
        float4 v = *(const float4*)(emb + (size_t)tok*Ee + threadIdx.x*4);
        *(float4*)(x + off) = v;
        __half h0,l0,h1,l1,h2,l2,h3,l3;
        hsplit(v.x,h0,l0); hsplit(v.y,h1,l1); hsplit(v.z,h2,l2); hsplit(v.w,h3,l3);
        *(__half2*)(xh + off)     = __halves2half2(h0,h1);
        *(__half2*)(xh + off + 2) = __halves2half2(h2,h3);
        *(__half2*)(xl + off)     = __halves2half2(l0,l1);
        *(__half2*)(xl + off + 2) = __halves2half2(l2,l3);
    }
}

// ================= fp16 split-precision mma.sync GEMM (512 threads) ==========
// Pass-major MMA ordering: all 8 output tiles per pass -> accumulator reuse
// distance 8 (was 1), breaking HMMA RAW chains. Per-acc pass order unchanged
// (hh, hl, lh) -> bit-identical results.
#define KC 32
#define SSTR 40
#define TILEH (128*SSTR)
#define TEN_B (TILEH*2)
#define GEMM_SMEM_BYTES (2*4*TEN_B)    // 81920

__device__ __forceinline__ void mma16816(float* c, const uint32_t* a, const uint32_t* b){
    asm volatile("mma.sync.aligned.m16n8k16.row.col.f32.f16.f16.f32 "
        "{%0,%1,%2,%3}, {%4,%5,%6,%7}, {%8,%9}, {%0,%1,%2,%3};"
        : "+f"(c[0]), "+f"(c[1]), "+f"(c[2]), "+f"(c[3])
        : "r"(a[0]), "r"(a[1]), "r"(a[2]), "r"(a[3]), "r"(b[0]), "r"(b[1]));
}
#define LDSM4(r0,r1,r2,r3,addr) \
    asm volatile("ldmatrix.sync.aligned.m8n8.x4.shared.b16 {%0,%1,%2,%3}, [%4];" \
        : "=r"(r0), "=r"(r1), "=r"(r2), "=r"(r3) : "r"(addr))
#define LDSM4T(r0,r1,r2,r3,addr) \
    asm volatile("ldmatrix.sync.aligned.m8n8.x4.trans.shared.b16 {%0,%1,%2,%3}, [%4];" \
        : "=r"(r0), "=r"(r1), "=r"(r2), "=r"(r3) : "r"(addr))

__global__ __launch_bounds__(512, 1)
void gemm_tc_kernel(const __half* __restrict__ Ahg, const __half* __restrict__ Alg,
                    const __half* __restrict__ Whg, const __half* __restrict__ Wlg,
                    const float* __restrict__ bias,
                    float* __restrict__ C,
                    __half* __restrict__ Chi, __half* __restrict__ Clo,
                    int N, int K, int doRelu){
    __half* sm = (__half*)dynsmem;
    uint32_t sb = s2u(dynsmem);
    int tid = threadIdx.x, wid = tid >> 5, lane = tid & 31;
    int warpM = wid >> 2, warpN = wid & 3;
    int rowBase = blockIdx.y * 128, colBase = blockIdx.x * 128;

    int srow = tid >> 2;
    int skq  = (tid & 3) * 8;
    const __half* aSh = Ahg + (size_t)(rowBase + srow)*K + skq;
    const __half* aSl = Alg + (size_t)(rowBase + srow)*K + skq;
    const __half* wSh = Whg + (size_t)(colBase + srow)*K + skq;
    const __half* wSl = Wlg + (size_t)(colBase + srow)*K + skq;
    int sbase = srow*SSTR + skq;

    uint32_t arow_off = (uint32_t)((warpM*32 + (lane & 15))*SSTR*2 + (lane >> 4)*16);
    uint32_t brow_off = (uint32_t)((warpN*32 + (lane >> 4)*8 + (lane & 7))*SSTR*2
                                   + ((lane >> 3) & 1)*16);

    float acc[2][4][4];
#pragma unroll
    for (int i = 0; i < 2; i++)
#pragma unroll
        for (int j = 0; j < 4; j++)
#pragma unroll
            for (int q = 0; q < 4; q++) acc[i][j][q] = 0.f;

    {
        __half* B0 = sm;
        *(uint4*)(B0 + sbase)           = *(const uint4*)(aSh);
        *(uint4*)(B0 + TILEH + sbase)   = *(const uint4*)(aSl);
        *(uint4*)(B0 + 2*TILEH + sbase) = *(const uint4*)(wSh);
        *(uint4*)(B0 + 3*TILEH + sbase) = *(const uint4*)(wSl);
    }
    __syncthreads();

    int nch = K / KC;
    for (int c = 0; c < nch; c++){
        if (c + 1 < nch){
            __half* nB = sm + ((c+1) & 1)*4*TILEH;
            *(uint4*)(nB + sbase)           = *(const uint4*)(aSh + (c+1)*KC);
            *(uint4*)(nB + TILEH + sbase)   = *(const uint4*)(aSl + (c+1)*KC);
            *(uint4*)(nB + 2*TILEH + sbase) = *(const uint4*)(wSh + (c+1)*KC);
            *(uint4*)(nB + 3*TILEH + sbase) = *(const uint4*)(wSl + (c+1)*KC);
        }

        uint32_t bufA = sb + (uint32_t)((c & 1)*4*TEN_B);
#pragma unroll
        for (int ks = 0; ks < 2; ks++){
            uint32_t kkb = (uint32_t)(ks*32);
            uint32_t aH = bufA + arow_off + kkb;
            uint32_t aL = aH + TEN_B;
            uint32_t bH = bufA + 2*TEN_B + brow_off + kkb;
            uint32_t bL = bH + TEN_B;

            uint32_t ah[2][4], al[2][4], bh[4][2], bl[4][2];
#pragma unroll
            for (int mt = 0; mt < 2; mt++){
                LDSM4(ah[mt][0], ah[mt][1], ah[mt][2], ah[mt][3], aH + mt*16*SSTR*2);
                LDSM4(al[mt][0], al[mt][1], al[mt][2], al[mt][3], aL + mt*16*SSTR*2);
            }
#pragma unroll
            for (int p = 0; p < 2; p++){
                LDSM4(bh[2*p][0], bh[2*p][1], bh[2*p+1][0], bh[2*p+1][1], bH + p*16*SSTR*2);
                LDSM4(bl[2*p][0], bl[2*p][1], bl[2*p+1][0], bl[2*p+1][1], bL + p*16*SSTR*2);
            }
            // pass-major: hh over all tiles, then hl, then lh
#pragma unroll
            for (int mt = 0; mt < 2; mt++)
#pragma unroll
                for (int nt = 0; nt < 4; nt++)
                    mma16816(acc[mt][nt], ah[mt], bh[nt]);
#pragma unroll
            for (int mt = 0; mt < 2; mt++)
#pragma unroll
                for (int nt = 0; nt < 4; nt++)
                    mma16816(acc[mt][nt], ah[mt], bl[nt]);
#pragma unroll
            for (int mt = 0; mt < 2; mt++)
#pragma unroll
                for (int nt = 0; nt < 4; nt++)
                    mma16816(acc[mt][nt], al[mt], bh[nt]);
        }
        __syncthreads();
    }

    int r  = lane >> 2;
    int cp = (lane & 3) * 2;
#pragma unroll
    for (int mt = 0; mt < 2; mt++){
        int r0 = rowBase + warpM*32 + mt*16 + r;
#pragma unroll
        for (int nt = 0; nt < 4; nt++){
            int c0 = colBase + warpN*32 + nt*8 + cp;
            float b0 = bias[c0], b1 = bias[c0+1];
            float v0 = acc[mt][nt][0] + b0, v1 = acc[mt][nt][1] + b1;
            float v2 = acc[mt][nt][2] + b0, v3 = acc[mt][nt][3] + b1;
            if (doRelu){
                v0 = fmaxf(v0, 0.f); v1 = fmaxf(v1, 0.f);
                v2 = fmaxf(v2, 0.f); v3 = fmaxf(v3, 0.f);
            }
            if (C){
                *(float2*)(C + (size_t)r0*N + c0)     = make_float2(v0, v1);
                *(float2*)(C + (size_t)(r0+8)*N + c0) = make_float2(v2, v3);
            }
            if (Chi){
                __half h0,l0,h1,l1,h2,l2,h3,l3;
                hsplit(v0,h0,l0); hsplit(v1,h1,l1); hsplit(v2,h2,l2); hsplit(v3,h3,l3);
                *(__half2*)(Chi + (size_t)r0*N + c0)     = __halves2half2(h0,h1);
                *(__half2*)(Chi + (size_t)(r0+8)*N + c0) = __halves2half2(h2,h3);
                *(__half2*)(Clo + (size_t)r0*N + c0)     = __halves2half2(l0,l1);
                *(__half2*)(Clo + (size_t)(r0+8)*N + c0) = __halves2half2(l2,l3);
            }
        }
    }
}

// ---------------- suffix-V sums per (b,h): SV[j] = sum_{t>=j} V[t] -----------
__global__ void svsum_kernel(const float* __restrict__ qkv, float* __restrict__ sv){
    __shared__ float segsum[8][64];
    int bh = blockIdx.x, b = bh >> 3, h = bh & 7;
    const float* vbase = qkv + (size_t)b*Tt*QKVDIM + h*HCH + 2*DH;
    int seg = threadIdx.x >> 6, d = threadIdx.x & 63;
    int j0 = seg * 128;
    float acc = 0.f;
    for (int j = j0; j < j0 + 128; j++) acc += vbase[(size_t)j*QKVDIM + d];
    segsum[seg][d] = acc;
    __syncthreads();
    float tl = 0.f;
    for (int s2 = seg + 1; s2 < 8; s2++) tl += segsum[s2][d];
    float* svb = sv + (size_t)bh*Tt*DH;
    acc = tl;
    for (int j = j0 + 127; j >= j0; j--) {
        acc += vbase[(size_t)j*QKVDIM + d];
        svb[(size_t)j*DH + d] = acc;
    }
}

// ================= flash attention via mma.sync (R15-validated) ==============
// Causal tiles only + analytic masked tail (l += T-1-qi, O += SV[qi+1]).
// Heavy q-tiles launch first (reversed blockIdx.y) for wave balance.
#define QSTR 72
#define ATILE_H (64*QSTR)
#define ATILE_B (ATILE_H*2)            // 9216 bytes
#define SM_QH 0
#define SM_QL ATILE_B
#define SM_KV (2*ATILE_B)
#define KVBUF_B (4*ATILE_B)
#define FLASH_SMEM (SM_KV + 2*KVBUF_B) // 92160

__global__ __launch_bounds__(128, 1)
void flash_attn_kernel(const __half* __restrict__ qkvh, const __half* __restrict__ qkvl,
                       const float* __restrict__ sv,
                       __half* __restrict__ oh, __half* __restrict__ ol){
    __half* sm = (__half*)dynsmem;
    uint32_t sb = s2u(dynsmem);
    int tid = threadIdx.x, wid = tid >> 5, lane = tid & 31;
    int bh = blockIdx.x, b = bh >> 3, h = bh & 7;
    int qt = (gridDim.y - 1) - blockIdx.y;   // heavy tiles first

    int srow = tid >> 1;
    int scol = (tid & 1) * 32;
    size_t qtokoff = (size_t)(b*Tt + qt*64 + srow)*QKVDIM + h*HCH + scol;
    int sdst = srow*QSTR + scol;

    // stage Q (hi/lo) once
    {
        const __half* qh = qkvh + qtokoff;
        const __half* ql = qkvl + qtokoff;
        __half* dQh = sm + SM_QH/2;
        __half* dQl = sm + SM_QL/2;
#pragma unroll
        for (int i = 0; i < 4; i++){
            *(uint4*)(dQh + sdst + i*8) = *(const uint4*)(qh + i*8);
            *(uint4*)(dQl + sdst + i*8) = *(const uint4*)(ql + i*8);
        }
    }
    // stage KV tile 0 into buffer 0
    {
        size_t ktok = (size_t)(b*Tt + srow)*QKVDIM + h*HCH + DH + scol;
        size_t vtok = ktok + DH;
        __half* base = sm + SM_KV/2;
#pragma unroll
        for (int i = 0; i < 4; i++){
            *(uint4*)(base + sdst + i*8)             = *(const uint4*)(qkvh + ktok + i*8);
            *(uint4*)(base + ATILE_H + sdst + i*8)   = *(const uint4*)(qkvl + ktok + i*8);
            *(uint4*)(base + 2*ATILE_H + sdst + i*8) = *(const uint4*)(qkvh + vtok + i*8);
            *(uint4*)(base + 3*ATILE_H + sdst + i*8) = *(const uint4*)(qkvl + vtok + i*8);
        }
    }
    __syncthreads();

    int r  = lane >> 2;
    int cq = lane & 3;
    int qi0 = qt*64 + wid*16 + r;
    int qi1 = qi0 + 8;

    uint32_t aoff = (uint32_t)((wid*16 + (lane & 15))*QSTR*2 + (lane >> 4)*16);
    uint32_t boff = (uint32_t)(((lane >> 4)*8 + (lane & 7))*QSTR*2 + ((lane >> 3) & 1)*16);
    uint32_t voff = (uint32_t)((lane & 15)*QSTR*2 + (lane >> 4)*16);

    float O[8][4];
#pragma unroll
    for (int i = 0; i < 8; i++)
#pragma unroll
        for (int q = 0; q < 4; q++) O[i][q] = 0.f;
    float l0 = 0.f, l1 = 0.f;

    for (int jt = 0; jt <= qt; jt++){
        if (jt + 1 <= qt){
            size_t ktok = (size_t)(b*Tt + (jt+1)*64 + srow)*QKVDIM + h*HCH + DH + scol;
            size_t vtok = ktok + DH;
            __half* base = sm + SM_KV/2 + ((jt+1) & 1)*(KVBUF_B/2);
#pragma unroll
            for (int i = 0; i < 4; i++){
                *(uint4*)(base + sdst + i*8)             = *(const uint4*)(qkvh + ktok + i*8);
                *(uint4*)(base + ATILE_H + sdst + i*8)   = *(const uint4*)(qkvl + ktok + i*8);
                *(uint4*)(base + 2*ATILE_H + sdst + i*8) = *(const uint4*)(qkvh + vtok + i*8);
                *(uint4*)(base + 3*ATILE_H + sdst + i*8) = *(const uint4*)(qkvl + vtok + i*8);
            }
        }

        uint32_t kvb = sb + SM_KV + (uint32_t)((jt & 1)*KVBUF_B);
        uint32_t KH = kvb, KL = kvb + ATILE_B, VH = kvb + 2*ATILE_B, VL = kvb + 3*ATILE_B;

        // ---- S = Q@K^T (3-pass hi/lo), fp32 accum ----
        float S[8][4];
#pragma unroll
        for (int i = 0; i < 8; i++)
#pragma unroll
            for (int q = 0; q < 4; q++) S[i][q] = 0.f;

#pragma unroll
        for (int ks = 0; ks < 4; ks++){
            uint32_t kb = (uint32_t)(ks*32);
            uint32_t ah[4], al[4], bh[4][2], bl[4][2];
            LDSM4(ah[0], ah[1], ah[2], ah[3], sb + SM_QH + aoff + kb);
            LDSM4(al[0], al[1], al[2], al[3], sb + SM_QL + aoff + kb);
#pragma unroll
            for (int p = 0; p < 2; p++){
                LDSM4(bh[2*p][0], bh[2*p][1], bh[2*p+1][0], bh[2*p+1][1],
                      KH + boff + kb + p*16*QSTR*2);
                LDSM4(bl[2*p][0], bl[2*p][1], bl[2*p+1][0], bl[2*p+1][1],
                      KL + boff + kb + p*16*QSTR*2);
            }
#pragma unroll
            for (int p = 0; p < 2; p++){
#pragma unroll
                for (int q2 = 0; q2 < 2; q2++){
                    int nt = 2*p + q2;
                    mma16816(S[nt], ah, bh[nt]);
                    mma16816(S[nt], ah, bl[nt]);
                    mma16816(S[nt], al, bh[nt]);
                }
            }
#pragma unroll
            for (int p = 0; p < 2; p++){
                uint32_t b2h[2][2], b2l[2][2];
                LDSM4(b2h[0][0], b2h[0][1], b2h[1][0], b2h[1][1],
                      KH + boff + kb + (p+2)*16*QSTR*2);
                LDSM4(b2l[0][0], b2l[0][1], b2l[1][0], b2l[1][1],
                      KL + boff + kb + (p+2)*16*QSTR*2);
#pragma unroll
                for (int q2 = 0; q2 < 2; q2++){
                    int nt = 4 + 2*p + q2;
                    mma16816(S[nt], ah, b2h[q2]);
                    mma16816(S[nt], ah, b2l[q2]);
                    mma16816(S[nt], al, b2h[q2]);
                }
            }
        }

        // ---- mask + exp + l + fp16 P ----
        uint32_t P[4][4];
#pragma unroll
        for (int n = 0; n < 8; n++){
            int colb = jt*64 + n*8 + cq*2;
            float e0 = __expf(fminf(S[n][0]*0.125f, 80.f));
            float e1 = __expf(fminf(S[n][1]*0.125f, 80.f));
            float e2 = __expf(fminf(S[n][2]*0.125f, 80.f));
            float e3 = __expf(fminf(S[n][3]*0.125f, 80.f));
            float p0 = (colb     <= qi0) ? e0 : 0.f;
            float p1 = (colb + 1 <= qi0) ? e1 : 0.f;
            float p2 = (colb     <= qi1) ? e2 : 0.f;
            float p3 = (colb + 1 <= qi1) ? e3 : 0.f;
            l0 += p0 + p1;
            l1 += p2 + p3;
            uint32_t h01, h23;
            asm("cvt.rn.f16x2.f32 %0, %1, %2;" : "=r"(h01) : "f"(p1), "f"(p0));
            asm("cvt.rn.f16x2.f32 %0, %1, %2;" : "=r"(h23) : "f"(p3), "f"(p2));
            int ks2 = n >> 1;
            if ((n & 1) == 0){ P[ks2][0] = h01; P[ks2][1] = h23; }
            else             { P[ks2][2] = h01; P[ks2][3] = h23; }
        }

        // ---- O += P@V (2-pass: Vh, Vl) ----
#pragma unroll
        for (int ks = 0; ks < 4; ks++){
            uint32_t krow = (uint32_t)(ks*16*QSTR*2);
#pragma unroll
            for (int p = 0; p < 4; p++){
                uint32_t bvh[2][2], bvl[2][2];
                LDSM4T(bvh[0][0], bvh[0][1], bvh[1][0], bvh[1][1],
                       VH + krow + voff + p*32);
                LDSM4T(bvl[0][0], bvl[0][1], bvl[1][0], bvl[1][1],
                       VL + krow + voff + p*32);
                mma16816(O[2*p],   P[ks], bvh[0]);
                mma16816(O[2*p],   P[ks], bvl[0]);
                mma16816(O[2*p+1], P[ks], bvh[1]);
                mma16816(O[2*p+1], P[ks], bvl[1]);
            }
        }
        __syncthreads();
    }

    // quad-reduce l
    unsigned qmask = 0xFu << (lane & 28);
    l0 += __shfl_xor_sync(qmask, l0, 1); l0 += __shfl_xor_sync(qmask, l0, 2);
    l1 += __shfl_xor_sync(qmask, l1, 1); l1 += __shfl_xor_sync(qmask, l1, 2);

    // analytic masked tail
    l0 += (float)(Tt - 1 - qi0);
    l1 += (float)(Tt - 1 - qi1);
    {
        const float* svb = sv + (size_t)bh*Tt*DH;
        float m0 = (qi0 < Tt-1) ? 1.f : 0.f;
        float m1 = (qi1 < Tt-1) ? 1.f : 0.f;
        int i0 = (qi0 < Tt-1) ? qi0+1 : Tt-1;
        int i1 = (qi1 < Tt-1) ? qi1+1 : Tt-1;
#pragma unroll
        for (int n = 0; n < 8; n++){
            int d0 = n*8 + cq*2;
            float2 s0 = *(const float2*)(svb + (size_t)i0*DH + d0);
            float2 s1 = *(const float2*)(svb + (size_t)i1*DH + d0);
            O[n][0] += m0*s0.x; O[n][1] += m0*s0.y;
            O[n][2] += m1*s1.x; O[n][3] += m1*s1.y;
        }
    }

    float inv0 = 1.f / l0, inv1 = 1.f / l1;
    size_t ob0 = (size_t)(b*Tt + qi0)*Ee + h*DH;
    size_t ob1 = (size_t)(b*Tt + qi1)*Ee + h*DH;
#pragma unroll
    for (int n = 0; n < 8; n++){
        int d0 = n*8 + cq*2;
        float v0 = O[n][0]*inv0, v1 = O[n][1]*inv0;
        float v2 = O[n][2]*inv1, v3 = O[n][3]*inv1;
        __half h0,lo0,h1,lo1,h2,lo2,h3,lo3;
        hsplit(v0,h0,lo0); hsplit(v1,h1,lo1); hsplit(v2,h2,lo2); hsplit(v3,h3,lo3);
        *(__half2*)(oh + ob0 + d0) = __halves2half2(h0,h1);
        *(__half2*)(ol + ob0 + d0) = __halves2half2(lo0,lo1);
        *(__half2*)(oh + ob1 + d0) = __halves2half2(h2,h3);
        *(__half2*)(ol + ob1 + d0) = __halves2half2(lo2,lo3);
    }
}

// ---------------- fused residual-add + LayerNorm (fp32 + hi/lo out) ----------
__global__ void add_ln_kernel(const float* __restrict__ a, const float* __restrict__ b,
                              const float* __restrict__ gam, const float* __restrict__ bet,
                              float* __restrict__ out,
                              __half* __restrict__ outh, __half* __restrict__ outl){
    int warp = threadIdx.x >> 5, lane = threadIdx.x & 31;
    int row = blockIdx.x * 8 + warp;
    size_t rb = (size_t)row*Ee;
    float xs[16];
    float sum = 0.f, sq = 0.f;
#pragma unroll
    for (int c = 0; c < 4; c++) {
        size_t off = rb + c*128 + lane*4;
        float4 va = *(const float4*)(a + off);
        float4 vb = *(const float4*)(b + off);
        float x0 = va.x+vb.x, x1 = va.y+vb.y, x2 = va.z+vb.z, x3 = va.w+vb.w;
        xs[c*4+0]=x0; xs[c*4+1]=x1; xs[c*4+2]=x2; xs[c*4+3]=x3;
        sum += x0+x1+x2+x3;
        sq  += x0*x0+x1*x1+x2*x2+x3*x3;
    }
    sum = warp_sum(sum);
    sq  = warp_sum(sq);
    float mean = sum * (1.f/(float)Ee);
    float var  = sq  * (1.f/(float)Ee) - mean*mean;
    float r = rsqrtf(var + 1e-5f);
#pragma unroll
    for (int c = 0; c < 4; c++) {
        int col = c*128 + lane*4;
        float4 g  = *(const float4*)(gam + col);
        float4 be = *(const float4*)(bet + col);
        float y0 = (xs[c*4+0]-mean)*r*g.x + be.x;
        float y1 = (xs[c*4+1]-mean)*r*g.y + be.y;
        float y2 = (xs[c*4+2]-mean)*r*g.z + be.z;
        float y3 = (xs[c*4+3]-mean)*r*g.w + be.w;
        *(float4*)(out + rb + col) = make_float4(y0,y1,y2,y3);
        __half h0,l0,h1,l1,h2,l2,h3,l3;
        hsplit(y0,h0,l0); hsplit(y1,h1,l1); hsplit(y2,h2,l2); hsplit(y3,h3,l3);
        *(__half2*)(outh + rb + col)     = __halves2half2(h0,h1);
        *(__half2*)(outh + rb + col + 2) = __halves2half2(h2,h3);
        *(__half2*)(outl + rb + col)     = __halves2half2(l0,l1);
        *(__half2*)(outl + rb + col + 2) = __halves2half2(l2,l3);
    }
}

// ---------------- loss -------------------------------------------------------
__global__ void loss_rows_kernel(const float* __restrict__ logits,
                                 const void* __restrict__ tgt,
                                 float* __restrict__ partials){
    __shared__ float rvals[8];
    int warp = threadIdx.x >> 5, lane = threadIdx.x & 31;
    int row = blockIdx.x * 8 + warp;
    const float* lp = logits + (size_t)row*Vv;
    float4 v = *(const float4*)(lp + lane*4);
    float mx = warp_max(fmaxf(fmaxf(v.x, v.y), fmaxf(v.z, v.w)));
    float sm = warp_sum(v.x + v.y + v.z + v.w);
    float se = warp_sum(__expf(v.x-mx) + __expf(v.y-mx) + __expf(v.z-mx) + __expf(v.w-mx));
    if (lane == 0) {
        float logZ = mx + logf(se);
        int t = get_tok(tgt, row);
        float nll    = logZ - lp[t];
        float smooth = logZ - sm * (1.f/(float)Vv);
        rvals[warp] = 0.9f*nll + 0.1f*smooth;
    }
    __syncthreads();
    if (threadIdx.x == 0) {
        float s = 0.f;
        for (int i = 0; i < 8; i++) s += rvals[i];
        partials[blockIdx.x] = s;
    }
}

__global__ void loss_final_kernel(const float* __restrict__ partials, float* __restrict__ out){
    __shared__ float s[512];
    int tid = threadIdx.x;
    s[tid] = partials[tid];
    __syncthreads();
    for (int o = 256; o; o >>= 1) {
        if (tid < o) s[tid] += s[tid + o];
        __syncthreads();
    }
    if (tid == 0) out[0] = s[0] * (1.f/(float)NTOK);
}

// ---------------- launch ------------------------------------------------------
extern "C" void kernel_launch(void* const* d_in, const int* in_sizes, int n_in,
                              void* d_out, int out_size){
    const void *inputs, *targets;
    const float *emb, *qkv_w, *qkv_b, *aff1_w, *aff1_b, *aff2_w, *aff2_b;
    const float *ffn1_w, *ffn1_b, *ffn2_w, *ffn2_b;
    const float *ln1_s, *ln1_b, *ln2_s, *ln2_b, *head_w, *head_b;

    if (in_sizes[1] > 100000) {
        aff1_b = (const float*)d_in[0];
        aff1_w = (const float*)d_in[1];
        aff2_b = (const float*)d_in[2];
        aff2_w = (const float*)d_in[3];
        emb    = (const float*)d_in[4];
        ffn1_b = (const float*)d_in[5];
        ffn1_w = (const float*)d_in[6];
        ffn2_b = (const float*)d_in[7];
        ffn2_w = (const float*)d_in[8];
        head_b = (const float*)d_in[9];
        head_w = (const float*)d_in[10];
        inputs = d_in[11];
        ln1_b  = (const float*)d_in[12];
        ln1_s  = (const float*)d_in[13];
        ln2_b  = (const float*)d_in[14];
        ln2_s  = (const float*)d_in[15];
        qkv_b  = (const float*)d_in[16];
        qkv_w  = (const float*)d_in[17];
        targets= d_in[18];
    } else {
        inputs  = d_in[0];
        targets = d_in[1];
        emb     = (const float*)d_in[2];
        qkv_w   = (const float*)d_in[3];
        qkv_b   = (const float*)d_in[4];
        aff1_w  = (const float*)d_in[5];
        aff1_b  = (const float*)d_in[6];
        aff2_w  = (const float*)d_in[7];
        aff2_b  = (const float*)d_in[8];
        ffn1_w  = (const float*)d_in[9];
        ffn1_b  = (const float*)d_in[10];
        ffn2_w  = (const float*)d_in[11];
        ffn2_b  = (const float*)d_in[12];
        ln1_s   = (const float*)d_in[13];
        ln1_b   = (const float*)d_in[14];
        ln2_s   = (const float*)d_in[15];
        ln2_b   = (const float*)d_in[16];
        head_w  = (const float*)d_in[17];
        head_b  = (const float*)d_in[18];
    }
    float* out = (float*)d_out;

    float *x, *qkv, *aff, *out1, *sv, *logits_scratch, *partials;
    __half *wh, *wl, *xh, *xl, *atth, *attl, *tmph, *tmpl, *o1h, *o1l, *qkvh, *qkvl;
    cudaGetSymbolAddress((void**)&x,    g_x);
    cudaGetSymbolAddress((void**)&qkv,  g_qkv);
    cudaGetSymbolAddress((void**)&aff,  g_aff);
    cudaGetSymbolAddress((void**)&out1, g_out1);
    cudaGetSymbolAddress((void**)&sv,   g_sv);
    cudaGetSymbolAddress((void**)&logits_scratch, g_logits);
    cudaGetSymbolAddress((void**)&partials, g_partials);
    cudaGetSymbolAddress((void**)&wh,   g_wh);
    cudaGetSymbolAddress((void**)&wl,   g_wl);
    cudaGetSymbolAddress((void**)&xh,   g_xh);
    cudaGetSymbolAddress((void**)&xl,   g_xl);
    cudaGetSymbolAddress((void**)&atth, g_atth);
    cudaGetSymbolAddress((void**)&attl, g_attl);
    cudaGetSymbolAddress((void**)&tmph, g_tmph);
    cudaGetSymbolAddress((void**)&tmpl, g_tmpl);
    cudaGetSymbolAddress((void**)&o1h,  g_o1h);
    cudaGetSymbolAddress((void**)&o1l,  g_o1l);
    cudaGetSymbolAddress((void**)&qkvh, g_qkvh);
    cudaGetSymbolAddress((void**)&qkvl, g_qkvl);

    const int BTV = NTOK * Vv;
    float* logits_dst = (out_size >= BTV) ? out : logits_scratch;
    float* loss_dst   = (out_size > BTV) ? (out + BTV)
                       : ((out_size > 0 && out_size < BTV) ? out : nullptr);

    cudaFuncSetAttribute(gemm_tc_kernel, cudaFuncAttributeMaxDynamicSharedMemorySize, GEMM_SMEM_BYTES);
    cudaFuncSetAttribute(flash_attn_kernel, cudaFuncAttributeMaxDynamicSharedMemorySize, FLASH_SMEM);

    prep_kernel<<<18496, 256>>>(qkv_w, aff1_w, aff2_w, ffn1_w, ffn2_w, head_w,
                                wh, wl, inputs, emb, x, xh, xl);

    dim3 gQKV(QKVDIM/128, NTOK/128);
    dim3 gE  (Ee/128,     NTOK/128);
    dim3 gHead(Vv/128,    NTOK/128);
    dim3 gAtt(Bsz*Hh, Tt/64);          // (32,16)

    for (int l = 0; l < Ll; l++) {
        gemm_tc_kernel<<<gQKV, 512, GEMM_SMEM_BYTES>>>(
            xh, xl, wh + (size_t)l*QKVDIM*Ee, wl + (size_t)l*QKVDIM*Ee,
            qkv_b + (size_t)l*QKVDIM, qkv, qkvh, qkvl, QKVDIM, Ee, 0);
        svsum_kernel<<<Bsz*Hh, 512>>>(qkv, sv);
        flash_attn_kernel<<<gAtt, 128, FLASH_SMEM>>>(qkvh, qkvl, sv, atth, attl);
        gemm_tc_kernel<<<gE, 512, GEMM_SMEM_BYTES>>>(
            atth, attl, wh + OFF_AFF1 + (size_t)l*Ee*Ee, wl + OFF_AFF1 + (size_t)l*Ee*Ee,
            aff1_b + (size_t)l*Ee, nullptr, tmph, tmpl, Ee, Ee, 1);
        gemm_tc_kernel<<<gE, 512, GEMM_SMEM_BYTES>>>(
            tmph, tmpl, wh + OFF_AFF2 + (size_t)l*Ee*Ee, wl + OFF_AFF2 + (size_t)l*Ee*Ee,
            aff2_b + (size_t)l*Ee, aff, nullptr, nullptr, Ee, Ee, 0);
        add_ln_kernel<<<NTOK/8, 256>>>(aff, x, ln1_s + (size_t)l*Ee, ln1_b + (size_t)l*Ee,
                                       out1, o1h, o1l);
        gemm_tc_kernel<<<gE, 512, GEMM_SMEM_BYTES>>>(
            o1h, o1l, wh + OFF_FFN1 + (size_t)l*Ee*Ee, wl + OFF_FFN1 + (size_t)l*Ee*Ee,
            ffn1_b + (size_t)l*Ee, nullptr, tmph, tmpl, Ee, Ee, 1);
        gemm_tc_kernel<<<gE, 512, GEMM_SMEM_BYTES>>>(
            tmph, tmpl, wh + OFF_FFN2 + (size_t)l*Ee*Ee, wl + OFF_FFN2 + (size_t)l*Ee*Ee,
            ffn2_b + (size_t)l*Ee, aff, nullptr, nullptr, Ee, Ee, 0);
        add_ln_kernel<<<NTOK/8, 256>>>(out1, aff, ln2_s + (size_t)l*Ee, ln2_b + (size_t)l*Ee,
                                       x, xh, xl);
    }

    gemm_tc_kernel<<<gHead, 512, GEMM_SMEM_BYTES>>>(
        xh, xl, wh + OFF_HEAD, wl + OFF_HEAD, head_b,
        logits_dst, nullptr, nullptr, Vv, Ee, 0);
    loss_rows_kernel<<<NTOK/8, 256>>>(logits_dst, targets, partials);
    if (loss_dst)
        loss_final_kernel<<<1, 512>>>(partials, loss_dst);
}